// round 8
// baseline (speedup 1.0000x reference)
#include <cuda_runtime.h>
#include <cuda_fp16.h>
#include <cstdint>

// ---------------- problem constants ----------------
#define M_ 4096
#define K_ 4096
#define N_ 11008
#define G_ 128

#define KITERS 64            // K_/64 k-chunks
#define MT_ 32               // M_/128 activation tiles
#define NT_ 43               // N_/256 weight tiles
#define NTILES (NT_ * MT_)   // 1376
#define FULLS  1332          // 148 * 9 full tiles
#define HALves (NTILES - FULLS)          // 44 leftover -> 88 half tiles
#define GRID_GEMM (FULLS + 2 * HALves)   // 1420

#define A_TILE_BYTES 16384   // 128 rows (m) x 128B (64 fp16 k)
#define W_SMEM_BYTES 32768   // 256 rows (n) x 128B
#define STAGE_BYTES  (W_SMEM_BYTES + A_TILE_BYTES)   // 49152
#define STAGES 4
#define OFF_CTRL   (STAGES * STAGE_BYTES)            // 196608
#define OFF_FULL   (OFF_CTRL)
#define OFF_DONE   (OFF_FULL + 8 * STAGES)
#define SMEM_TOTAL (OFF_CTRL + 128)

#define SWZ(off) ((off) ^ (((off) >> 3) & 0x70))

// ---------------- scratch (static device array: allocation-free) ----------------
__device__ __align__(1024) __half g_a[(size_t)M_ * K_];   // ~32 MB, [mt][kc][swz 128x128B]

// ---------------- PTX helpers (base sm_103-safe) ----------------
__device__ __forceinline__ uint32_t smem_u32(const void* p) {
    uint32_t a;
    asm("{ .reg .u64 t; cvta.to.shared.u64 t, %1; cvt.u32.u64 %0, t; }" : "=r"(a) : "l"(p));
    return a;
}

#define MB_INIT(mbar, cnt) \
    asm volatile("mbarrier.init.shared.b64 [%0], %1;" :: "r"(mbar), "r"(cnt) : "memory")

#define MB_ARRIVE(mbar) \
    asm volatile("mbarrier.arrive.shared.b64 _, [%0];" :: "r"(mbar) : "memory")

#define MB_EXPECT_TX(mbar, bytes) \
    asm volatile("mbarrier.arrive.expect_tx.shared.b64 _, [%0], %1;" :: "r"(mbar), "r"(bytes) : "memory")

#define MB_WAIT(mbar, ph) do { \
    asm volatile("{\n\t.reg .pred P;\n\t" \
        "WL%=:\n\t" \
        "mbarrier.try_wait.parity.acquire.cta.shared::cta.b64 P, [%0], %1, 0x989680;\n\t" \
        "@P bra WD%=;\n\t" \
        "bra WL%=;\n\t" \
        "WD%=:\n\t}" :: "r"(mbar), "r"(ph) : "memory"); \
} while (0)

#define BULK_G2S(dst, src, bytes, mbar) \
    asm volatile("cp.async.bulk.shared::cluster.global.mbarrier::complete_tx::bytes [%0], [%1], %2, [%3];" \
        :: "r"(dst), "l"(src), "r"(bytes), "r"(mbar) : "memory")

#define LDSM4(r0, r1, r2, r3, addr) \
    asm volatile("ldmatrix.sync.aligned.m8n8.x4.shared.b16 {%0,%1,%2,%3}, [%4];" \
        : "=r"(r0), "=r"(r1), "=r"(r2), "=r"(r3) : "r"(addr))

#define MMA16816(acc, a0, a1, a2, a3, b0, b1) \
    asm volatile("mma.sync.aligned.m16n8k16.row.col.f32.f16.f16.f32 " \
        "{%0,%1,%2,%3}, {%4,%5,%6,%7}, {%8,%9}, {%0,%1,%2,%3};" \
        : "+f"((acc)[0]), "+f"((acc)[1]), "+f"((acc)[2]), "+f"((acc)[3]) \
        : "r"(a0), "r"(a1), "r"(a2), "r"(a3), "r"(b0), "r"(b1))

__device__ __forceinline__ unsigned pack2(float a, float b) {
    __half2 h = __floats2half2_rn(a, b);
    return *reinterpret_cast<unsigned*>(&h);
}

// ---------------- prepass A: fp32 -> fp16, 128-row tile panels + SW128 ----------------
// grid (KITERS, MT_), 256 threads
__global__ void prep_a_kernel(const float* __restrict__ in) {
    int kc = blockIdx.x, mt = blockIdx.y, tid = threadIdx.x;
    char* dstbase = (char*)g_a + (size_t)(mt * KITERS + kc) * A_TILE_BYTES;
    int cc = tid & 7;
#pragma unroll
    for (int it = 0; it < 4; it++) {
        int r = (tid >> 3) + it * 32;                 // 0..127 (m local)
        int m = mt * 128 + r;
        int k0 = kc * 64 + cc * 8;
        const float4* p = (const float4*)(in + (size_t)m * K_ + k0);
        float4 f0 = p[0], f1 = p[1];
        uint4 v;
        v.x = pack2(f0.x, f0.y); v.y = pack2(f0.z, f0.w);
        v.z = pack2(f1.x, f1.y); v.w = pack2(f1.z, f1.w);
        *(uint4*)(dstbase + SWZ(r * 128 + cc * 16)) = v;
    }
}

// ---------------- in-GEMM W dequant: one n-column per thread, 64 k per chunk ----------------
__device__ __forceinline__ void dequant_w(const int* __restrict__ qcol,
                                          const float* __restrict__ sc,
                                          const int* __restrict__ zp,
                                          int n_g, int c, uint32_t* h2) {
    int goff = (c >> 1) * N_ + n_g;
    float s = __ldg(sc + goff);
    float b = -(float)__ldg(zp + goff) * s;
    const int* p = qcol + c * 64 * N_;
#pragma unroll
    for (int kk = 0; kk < 32; kk++) {
        int q0 = __ldg(p + (2 * kk) * N_);
        int q1 = __ldg(p + (2 * kk + 1) * N_);
        h2[kk] = pack2(fmaf((float)q0, s, b), fmaf((float)q1, s, b));
    }
}

__device__ __forceinline__ void sts_w(uint32_t stg, int n_l, const uint32_t* h2) {
    uint32_t roff = (uint32_t)n_l * 128;
#pragma unroll
    for (int i = 0; i < 8; i++) {
        uint32_t addr = stg + SWZ(roff + i * 16);
        asm volatile("st.shared.v4.b32 [%0], {%1,%2,%3,%4};"
                     :: "r"(addr), "r"(h2[4 * i]), "r"(h2[4 * i + 1]),
                        "r"(h2[4 * i + 2]), "r"(h2[4 * i + 3]) : "memory");
    }
}

// ---------------- GEMM body (templated on half-tile mode), fused W dequant ----------------
// HALF=false: CTA 128(M) x 256(N), warp tile 64x64 (MI=4)
// HALF=true : CTA 128(M) x 128(N), warp tile 32x64 (MI=2)
template<bool HALF>
__device__ __forceinline__ void gemm_body(
    uint32_t sb,
    const int* __restrict__ q, const float* __restrict__ sc, const int* __restrict__ zp,
    const char* asrc, const float* __restrict__ bias, float* __restrict__ out,
    int nt, int mt, int halfsel)
{
    constexpr int MI = HALF ? 2 : 4;
    int tid = threadIdx.x, lane = tid & 31, wid = tid >> 5;
    int wm = HALF ? (wid & 3) : (wid & 1);
    int wn = HALF ? (wid >> 2) : (wid >> 1);

    uint32_t mb_full = sb + OFF_FULL;
    uint32_t mb_done = sb + OFF_DONE;

    bool act = HALF ? (tid < 128) : true;      // W-producer active?
    int n_l = tid;                              // local W smem row
    int n_g = nt * 256 + halfsel * 128 + n_l;   // global n of this thread's column
    const int* qcol = q + n_g;

    // ---- prologue: produce W for chunks 0..3 + bulk A ----
#pragma unroll 1
    for (int p = 0; p < STAGES; p++) {
        uint32_t stg = sb + p * STAGE_BYTES;
        if (act) {
            uint32_t h2[32];
            dequant_w(qcol, sc, zp, n_g, p, h2);
            sts_w(stg, n_l, h2);
        }
        if (tid == 0) {
            MB_EXPECT_TX(mb_full + 8 * p, (unsigned)A_TILE_BYTES);
            BULK_G2S(stg + W_SMEM_BYTES, asrc + (size_t)p * A_TILE_BYTES,
                     (unsigned)A_TILE_BYTES, mb_full + 8 * p);
        } else {
            MB_ARRIVE(mb_full + 8 * p);
        }
    }

    // per-thread ldmatrix row bases (stage-relative)
    uint32_t a_roff[MI], b_roff[4];
    uint32_t a_swz[MI], b_swz[4];
#pragma unroll
    for (int mi = 0; mi < MI; mi++) {
        int row = wm * (16 * MI) + mi * 16 + (lane & 15);
        a_roff[mi] = W_SMEM_BYTES + row * 128;        // A sits after W in stage
        a_swz[mi] = row & 7;
    }
#pragma unroll
    for (int nb = 0; nb < 4; nb++) {
        int row = wn * 64 + nb * 16 + (lane & 7) + ((lane >> 4) << 3);
        b_roff[nb] = row * 128;
        b_swz[nb] = row & 7;
    }
    uint32_t a_c = (lane >> 4);        // 0..1, A k-half within 16B cols
    uint32_t b_c = (lane >> 3) & 1;    // 0..1, B k-half

    float acc[MI][8][4];
#pragma unroll
    for (int mi = 0; mi < MI; mi++)
#pragma unroll
        for (int ni = 0; ni < 8; ni++)
#pragma unroll
            for (int e = 0; e < 4; e++) acc[mi][ni][e] = 0.f;

#pragma unroll 1
    for (int i = 0; i < KITERS; i++) {
        int s = i & (STAGES - 1);
        int ph = (i >> 2) & 1;
        MB_WAIT(mb_full + 8 * s, ph);
        uint32_t stg = sb + s * STAGE_BYTES;

        // ---- ks = 0, 1 ----
#pragma unroll
        for (int ks = 0; ks < 2; ks++) {
            uint32_t a[MI][4], b[4][4];
#pragma unroll
            for (int mi = 0; mi < MI; mi++) {
                uint32_t addr = stg + a_roff[mi] + (((ks * 2 + a_c) ^ a_swz[mi]) << 4);
                LDSM4(a[mi][0], a[mi][1], a[mi][2], a[mi][3], addr);
            }
#pragma unroll
            for (int nb = 0; nb < 4; nb++) {
                uint32_t addr = stg + b_roff[nb] + (((ks * 2 + b_c) ^ b_swz[nb]) << 4);
                LDSM4(b[nb][0], b[nb][1], b[nb][2], b[nb][3], addr);
            }
#pragma unroll
            for (int mi = 0; mi < MI; mi++)
#pragma unroll
                for (int ni = 0; ni < 8; ni++)
                    MMA16816(acc[mi][ni],
                             a[mi][0], a[mi][1], a[mi][2], a[mi][3],
                             b[ni >> 1][(ni & 1) * 2], b[ni >> 1][(ni & 1) * 2 + 1]);
        }

        // ---- mid-chunk: dequant next-next W into registers (latency hidden by ks2/ks3) ----
        int c2 = i + STAGES;
        bool produce = (c2 < KITERS);
        uint32_t h2[32];
        if (produce && act) dequant_w(qcol, sc, zp, n_g, c2, h2);

        // ---- ks = 2, 3 ----
#pragma unroll
        for (int ks = 2; ks < 4; ks++) {
            uint32_t a[MI][4], b[4][4];
#pragma unroll
            for (int mi = 0; mi < MI; mi++) {
                uint32_t addr = stg + a_roff[mi] + (((ks * 2 + a_c) ^ a_swz[mi]) << 4);
                LDSM4(a[mi][0], a[mi][1], a[mi][2], a[mi][3], addr);
            }
#pragma unroll
            for (int nb = 0; nb < 4; nb++) {
                uint32_t addr = stg + b_roff[nb] + (((ks * 2 + b_c) ^ b_swz[nb]) << 4);
                LDSM4(b[nb][0], b[nb][1], b[nb][2], b[nb][3], addr);
            }
#pragma unroll
            for (int mi = 0; mi < MI; mi++)
#pragma unroll
                for (int ni = 0; ni < 8; ni++)
                    MMA16816(acc[mi][ni],
                             a[mi][0], a[mi][1], a[mi][2], a[mi][3],
                             b[ni >> 1][(ni & 1) * 2], b[ni >> 1][(ni & 1) * 2 + 1]);
        }

        if (lane == 0) MB_ARRIVE(mb_done + 8 * s);

        if (produce) {
            MB_WAIT(mb_done + 8 * s, ph);     // all 8 warps done with this stage
            if (act) sts_w(stg, n_l, h2);
            if (tid == 0) {
                MB_EXPECT_TX(mb_full + 8 * s, (unsigned)A_TILE_BYTES);
                BULK_G2S(stg + W_SMEM_BYTES, asrc + (size_t)c2 * A_TILE_BYTES,
                         (unsigned)A_TILE_BYTES, mb_full + 8 * s);
            } else {
                MB_ARRIVE(mb_full + 8 * s);
            }
        }
    }

    // ---- epilogue: streaming coalesced float2 stores + bias ----
    int m0 = mt * 128 + wm * (16 * MI) + (lane >> 2);
    int n0 = nt * 256 + halfsel * 128 + wn * 64 + (lane & 3) * 2;
#pragma unroll
    for (int ni = 0; ni < 8; ni++) {
        int n = n0 + ni * 8;
        float2 bb = *(const float2*)(bias + n);
#pragma unroll
        for (int mi = 0; mi < MI; mi++) {
            int m = m0 + mi * 16;
            float2 v0 = make_float2(acc[mi][ni][0] + bb.x, acc[mi][ni][1] + bb.y);
            float2 v1 = make_float2(acc[mi][ni][2] + bb.x, acc[mi][ni][3] + bb.y);
            __stcs((float2*)(out + (size_t)m * N_ + n), v0);
            __stcs((float2*)(out + (size_t)(m + 8) * N_ + n), v1);
        }
    }
}

// ---------------- GEMM kernel: 1332 full tiles + 88 half tiles (tail smoothing) ----------------
// grid GRID_GEMM, 256 threads (8 warps), dyn smem SMEM_TOTAL
__global__ void __launch_bounds__(256, 1)
gemm_kernel(const int* __restrict__ q, const float* __restrict__ sc, const int* __restrict__ zp,
            const float* __restrict__ bias, float* __restrict__ out) {
    extern __shared__ char smem[];
    uint32_t sb = smem_u32(smem);
    int tid = threadIdx.x;
    int bid = blockIdx.x;

    uint32_t mb_full = sb + OFF_FULL;
    uint32_t mb_done = sb + OFF_DONE;
    if (tid == 0) {
        for (int s = 0; s < STAGES; s++) { MB_INIT(mb_full + 8 * s, 256); MB_INIT(mb_done + 8 * s, 8); }
    }
    __syncthreads();

    if (bid < FULLS) {
        int t = bid;
        int nt = t >> 5, mt = t & 31;     // 32 consecutive bids share one q panel (L2 reuse)
        const char* asrc = (const char*)g_a + (size_t)mt * KITERS * A_TILE_BYTES;
        gemm_body<false>(sb, q, sc, zp, asrc, bias, out, nt, mt, 0);
    } else {
        int idx = bid - FULLS;            // 0..87
        int t = FULLS + (idx >> 1);       // 1332..1375
        int halfsel = idx & 1;
        int nt = t >> 5, mt = t & 31;
        const char* asrc = (const char*)g_a + (size_t)mt * KITERS * A_TILE_BYTES;
        gemm_body<true>(sb, q, sc, zp, asrc, bias, out, nt, mt, halfsel);
    }
}

// ---------------- launch ----------------
extern "C" void kernel_launch(void* const* d_in, const int* in_sizes, int n_in,
                              void* d_out, int out_size) {
    const float* input   = (const float*)d_in[0];
    const int*   qweight = (const int*)d_in[1];
    const float* scales  = (const float*)d_in[2];
    const int*   qzeros  = (const int*)d_in[3];
    const float* bias    = (const float*)d_in[4];
    float* out = (float*)d_out;

    cudaFuncSetAttribute(gemm_kernel, cudaFuncAttributeMaxDynamicSharedMemorySize, SMEM_TOTAL);

    prep_a_kernel<<<dim3(KITERS, MT_), 256>>>(input);
    gemm_kernel<<<GRID_GEMM, 256, SMEM_TOTAL>>>(qweight, scales, qzeros, bias, out);
}